// round 7
// baseline (speedup 1.0000x reference)
#include <cuda_runtime.h>
#include <cuda_bf16.h>
#include <float.h>
#include <math.h>

// ---------------------------------------------------------------------------
// MEATransformer: top-3 retrieval over 500K cosine sims + tiny 2-layer
// transformer (768 seqs x 3 tokens x 256) + logits/retrieval mix.
// Round 6: software-pipelined sims kernel (cp.async double buffering,
// XOR-swizzled q tile), qkv/oproj widened to 16 rows/block.
// ---------------------------------------------------------------------------

#define NN       500000
#define DD       256
#define BB       256
#define KK       3
#define NLAB     12
#define CT       128            // columns per tile in sims kernel
#define NTILES   3907           // ceil(500000/128)
#define GX       148            // sims gridDim.x (partials width) = 2 exact waves
#define NSEQ     768            // B*K
#define MROWS    2304           // NSEQ*3 token rows

// ---------------- device scratch (no cudaMalloc allowed) -------------------
__device__ float g_qn   [BB * DD];
__device__ float g_pv   [BB * GX * 3];
__device__ int   g_pi   [BB * GX * 3];
__device__ float g_score[NSEQ];
__device__ int   g_idx  [NSEQ];
__device__ int   g_lab  [NSEQ];
__device__ float g_H    [MROWS * DD];
__device__ float g_Qb   [MROWS * DD];
__device__ float g_Kb   [MROWS * DD];
__device__ float g_Vb   [MROWS * DD];
__device__ float g_Ab   [MROWS * DD];
__device__ float g_x    [NSEQ * DD];

// ---------------- f32x2 / cp.async helpers ----------------------------------
__device__ __forceinline__ unsigned long long bcast2(float v) {
    unsigned long long r;
    asm("mov.b64 %0, {%1,%1};" : "=l"(r) : "f"(v));
    return r;
}
__device__ __forceinline__ void unpack2(unsigned long long v, float& lo, float& hi) {
    asm("mov.b64 {%0,%1}, %2;" : "=f"(lo), "=f"(hi) : "l"(v));
}
__device__ __forceinline__ void ffma2(unsigned long long& d,
                                      unsigned long long a,
                                      unsigned long long b) {
    asm("fma.rn.f32x2 %0, %1, %2, %0;" : "+l"(d) : "l"(a), "l"(b));
}
__device__ __forceinline__ void cp_async16(unsigned int dst, const void* src, int valid) {
    asm volatile("cp.async.cg.shared.global [%0], [%1], 16, %2;"
                 :: "r"(dst), "l"(src), "r"(valid));
}
__device__ __forceinline__ void cp_commit() {
    asm volatile("cp.async.commit_group;");
}
__device__ __forceinline__ void cp_wait0() {
    asm volatile("cp.async.wait_group 0;" ::: "memory");
}

// ---------------- top-3 helpers ----------------------------------------------
__device__ __forceinline__ bool better(float v1, int i1, float v2, int i2) {
    return (v1 > v2) || (v1 == v2 && i1 < i2);   // jax top_k: ties -> lower idx
}
__device__ __forceinline__ void ins3(float v, int i,
                                     float& v0, int& i0,
                                     float& v1, int& i1,
                                     float& v2, int& i2) {
    if (better(v, i, v2, i2)) {
        if (better(v, i, v1, i1)) {
            v2 = v1; i2 = i1;
            if (better(v, i, v0, i0)) { v1 = v0; i1 = i0; v0 = v; i0 = i; }
            else                      { v1 = v;  i1 = i; }
        } else { v2 = v; i2 = i; }
    }
}
__device__ __forceinline__ void merge3(float& a0, int& x0, float& a1, int& x1,
                                       float& a2, int& x2,
                                       float b0, int y0, float b1, int y1,
                                       float b2, int y2) {
    float o0, o1, o2; int p0, p1, p2;
    if (better(a0, x0, b0, y0)) { o0 = a0; p0 = x0; a0 = a1; x0 = x1; a1 = a2; x1 = x2; a2 = -FLT_MAX; x2 = 0x7fffffff; }
    else                        { o0 = b0; p0 = y0; b0 = b1; y0 = y1; b1 = b2; y1 = y2; b2 = -FLT_MAX; y2 = 0x7fffffff; }
    if (better(a0, x0, b0, y0)) { o1 = a0; p1 = x0; a0 = a1; x0 = x1; }
    else                        { o1 = b0; p1 = y0; b0 = b1; y0 = y1; }
    if (better(a0, x0, b0, y0)) { o2 = a0; p2 = x0; }
    else                        { o2 = b0; p2 = y0; }
    a0 = o0; x0 = p0; a1 = o1; x1 = p1; a2 = o2; x2 = p2;
}

// ---------------- kernel 1: normalize queries -------------------------------
__global__ void normalize_kernel(const float* __restrict__ q) {
    __shared__ float ws[8];
    int b = blockIdx.x, t = threadIdx.x;
    float v = q[b * DD + t];
    float s = v * v;
    #pragma unroll
    for (int o = 16; o; o >>= 1) s += __shfl_xor_sync(0xffffffffu, s, o);
    if ((t & 31) == 0) ws[t >> 5] = s;
    __syncthreads();
    float tot = 0.f;
    #pragma unroll
    for (int w = 0; w < 8; w++) tot += ws[w];
    g_qn[b * DD + t] = v / sqrtf(tot);
}

// ---------------- kernel 2: pipelined sims GEMM + streaming top-3 -----------
// 256 threads (16 tx x 16 ty); tile 64 queries x 128 columns; micro-tile
// 4 rows x 8 cols via f32x2. Double-buffered cp.async stages; q tile stored
// with 16B XOR swizzle so the 2-rows-per-warp broadcast reads hit distinct
// banks while cp.async keeps 16B-aligned destinations.
__global__ void __launch_bounds__(256, 2)
sims_topk_kernel(const float* __restrict__ w) {
    __shared__ float qs[2][64][32];    //  16 KB (stage-buffered, XOR swizzle)
    __shared__ float wsm[2][32][128];  //  32 KB (stage-buffered)

    const int tid = threadIdx.x;
    const int tx = tid & 15, ty = tid >> 4;
    const int qrow0 = blockIdx.y * 64;

    unsigned int qs_base, ws_base;
    {
        unsigned long long a = (unsigned long long)__cvta_generic_to_shared(&qs[0][0][0]);
        unsigned long long b = (unsigned long long)__cvta_generic_to_shared(&wsm[0][0][0]);
        qs_base = (unsigned int)a;
        ws_base = (unsigned int)b;
    }

    const int ntiles_mine = (NTILES - blockIdx.x + GX - 1) / GX;

    float tv[4][3]; int ti3[4][3];
    #pragma unroll
    for (int r = 0; r < 4; r++)
        #pragma unroll
        for (int j = 0; j < 3; j++) { tv[r][j] = -FLT_MAX; ti3[r][j] = 0x7fffffff; }

    // ---- stage issue: q (2 chunks) + w (4 chunks) of 16B per thread ----
    auto issue_stage = [&](int t, int dk, int buf) {
        #pragma unroll
        for (int j = 0; j < 2; j++) {
            int id = tid + j * 256;
            int r = id >> 3, c16 = id & 7;
            const float* src = g_qn + (qrow0 + r) * DD + dk * 32 + c16 * 4;
            unsigned int dst = qs_base + buf * 8192 + r * 128 + ((c16 ^ (r & 7)) << 4);
            cp_async16(dst, src, 16);
        }
        int col0 = t * CT;
        #pragma unroll
        for (int j = 0; j < 4; j++) {
            int id = tid + j * 256;
            int r = id >> 5, c16 = id & 31;
            int col = col0 + c16 * 4;
            const float* src = w + (long)(dk * 32 + r) * NN + col;
            unsigned int dst = ws_base + buf * 16384 + r * 512 + (c16 << 4);
            cp_async16(dst, src, col < NN ? 16 : 0);
        }
    };

    // prologue: stage 0 into buffer 0
    issue_stage(blockIdx.x, 0, 0);
    cp_commit();

    int t = blockIdx.x;
    const int ty4 = ty * 4;
    for (int ti = 0; ti < ntiles_mine; ti++, t += GX) {
        const int col0 = t * CT;
        unsigned long long acc[4][4];
        #pragma unroll
        for (int r = 0; r < 4; r++)
            #pragma unroll
            for (int p = 0; p < 4; p++) acc[r][p] = 0ull;

        for (int dk = 0; dk < 8; dk++) {
            const int buf = dk & 1;
            cp_wait0();
            __syncthreads();   // stage dk visible; all threads done with buf^1
            // issue next stage into buf^1
            if (dk < 7)                      issue_stage(t, dk + 1, buf ^ 1);
            else if (ti + 1 < ntiles_mine)   issue_stage(t + GX, 0, buf ^ 1);
            cp_commit();

            const float* qsf = &qs[buf][0][0];
            const float* wsf = &wsm[buf][0][0];
            #pragma unroll
            for (int d4 = 0; d4 < 8; d4++) {
                #pragma unroll
                for (int dd = 0; dd < 4; dd++) {
                    const int d = d4 * 4 + dd;
                    const ulonglong2 a = *(const ulonglong2*)(wsf + d * 128 + tx * 4);
                    const ulonglong2 b = *(const ulonglong2*)(wsf + d * 128 + 64 + tx * 4);
                    #pragma unroll
                    for (int rr = 0; rr < 4; rr++) {
                        const int rw = ty4 + rr;
                        float qf = qsf[rw * 32 + ((d4 ^ (rw & 7)) << 2) + dd];
                        unsigned long long qv = bcast2(qf);
                        ffma2(acc[rr][0], qv, a.x);
                        ffma2(acc[rr][1], qv, a.y);
                        ffma2(acc[rr][2], qv, b.x);
                        ffma2(acc[rr][3], qv, b.y);
                    }
                }
            }
        }
        // streaming top-3 insertion
        // acc[rr][0] -> cols col0+tx*4 +0/+1 ; acc[rr][1] -> +2/+3
        // acc[rr][2] -> cols col0+64+tx*4 +0/+1 ; acc[rr][3] -> +2/+3
        #pragma unroll
        for (int rr = 0; rr < 4; rr++) {
            #pragma unroll
            for (int p = 0; p < 4; p++) {
                float lo, hi;
                unpack2(acc[rr][p], lo, hi);
                int grp = p >> 1;
                int c0 = col0 + grp * 64 + tx * 4 + (p & 1) * 2;
                if (c0 < NN)
                    ins3(lo, c0, tv[rr][0], ti3[rr][0], tv[rr][1], ti3[rr][1], tv[rr][2], ti3[rr][2]);
                if (c0 + 1 < NN)
                    ins3(hi, c0 + 1, tv[rr][0], ti3[rr][0], tv[rr][1], ti3[rr][1], tv[rr][2], ti3[rr][2]);
            }
        }
    }

    #pragma unroll
    for (int rr = 0; rr < 4; rr++) {
        #pragma unroll
        for (int off = 8; off >= 1; off >>= 1) {
            float b0 = __shfl_xor_sync(0xffffffffu, tv[rr][0], off, 16);
            float b1 = __shfl_xor_sync(0xffffffffu, tv[rr][1], off, 16);
            float b2 = __shfl_xor_sync(0xffffffffu, tv[rr][2], off, 16);
            int   y0 = __shfl_xor_sync(0xffffffffu, ti3[rr][0], off, 16);
            int   y1 = __shfl_xor_sync(0xffffffffu, ti3[rr][1], off, 16);
            int   y2 = __shfl_xor_sync(0xffffffffu, ti3[rr][2], off, 16);
            merge3(tv[rr][0], ti3[rr][0], tv[rr][1], ti3[rr][1], tv[rr][2], ti3[rr][2],
                   b0, y0, b1, y1, b2, y2);
        }
        if (tx == 0) {
            int q = qrow0 + ty4 + rr;
            int base = (q * GX + blockIdx.x) * 3;
            #pragma unroll
            for (int j = 0; j < 3; j++) { g_pv[base + j] = tv[rr][j]; g_pi[base + j] = ti3[rr][j]; }
        }
    }
}

// ---------------- kernel 3: merge partial top-3 per query -------------------
// 160 threads (5 warps); lanes t >= GX hold neutral values.
__global__ void topk_merge_kernel(const int* __restrict__ label) {
    __shared__ float sv[5][3];
    __shared__ int   si[5][3];
    int b = blockIdx.x, t = threadIdx.x;
    float v0 = -FLT_MAX, v1 = -FLT_MAX, v2 = -FLT_MAX;
    int   i0 = 0x7fffffff, i1 = 0x7fffffff, i2 = 0x7fffffff;
    if (t < GX) {
        int base = (b * GX + t) * 3;
        v0 = g_pv[base];     i0 = g_pi[base];
        v1 = g_pv[base + 1]; i1 = g_pi[base + 1];
        v2 = g_pv[base + 2]; i2 = g_pi[base + 2];
    }
    #pragma unroll
    for (int off = 16; off >= 1; off >>= 1) {
        float b0 = __shfl_xor_sync(0xffffffffu, v0, off);
        float b1 = __shfl_xor_sync(0xffffffffu, v1, off);
        float b2 = __shfl_xor_sync(0xffffffffu, v2, off);
        int   y0 = __shfl_xor_sync(0xffffffffu, i0, off);
        int   y1 = __shfl_xor_sync(0xffffffffu, i1, off);
        int   y2 = __shfl_xor_sync(0xffffffffu, i2, off);
        merge3(v0, i0, v1, i1, v2, i2, b0, y0, b1, y1, b2, y2);
    }
    int warp = t >> 5;
    if ((t & 31) == 0) { sv[warp][0] = v0; si[warp][0] = i0; sv[warp][1] = v1; si[warp][1] = i1; sv[warp][2] = v2; si[warp][2] = i2; }
    __syncthreads();
    if (t == 0) {
        float f0 = -FLT_MAX, f1 = -FLT_MAX, f2 = -FLT_MAX;
        int   j0 = 0x7fffffff, j1 = 0x7fffffff, j2 = 0x7fffffff;
        for (int wp = 0; wp < 5; wp++)
            for (int e = 0; e < 3; e++)
                ins3(sv[wp][e], si[wp][e], f0, j0, f1, j1, f2, j2);
        float fv[3] = {f0, f1, f2}; int fi[3] = {j0, j1, j2};
        for (int k = 0; k < 3; k++) {
            g_score[b * 3 + k] = fv[k];
            g_idx[b * 3 + k]   = fi[k];
            g_lab[b * 3 + k]   = label[fi[k]];
        }
    }
}

// ---------------- kernel 4: build H (gather) ---------------------------------
__global__ void build_h_kernel(const float* __restrict__ queries,
                               const float* __restrict__ w) {
    int s = blockIdx.x;       // 0..767
    int d = threadIdx.x;      // 0..255
    int b = s / KK;
    int lab = g_lab[s];
    float score = g_score[s];
    int idx = g_idx[s];
    float* Hrow = &g_H[s * 3 * DD];
    Hrow[d]           = (d == lab) ? score : 0.f;   // CLS token
    Hrow[DD + d]      = queries[b * DD + d];        // query token
    Hrow[2 * DD + d]  = w[d * NN + idx];            // retrieved token
}

// ---------------- tail: fused Q/K/V matvec, 16 rows per block ----------------
__global__ void qkv_kernel(const float* __restrict__ Wq, const float* __restrict__ bq,
                           const float* __restrict__ Wk, const float* __restrict__ bk,
                           const float* __restrict__ Wv, const float* __restrict__ bv) {
    __shared__ float h[16][DD];
    int r0 = blockIdx.x * 16, t = threadIdx.x;
    #pragma unroll
    for (int i = 0; i < 16; i++) h[i][t] = g_H[(r0 + i) * DD + t];
    __syncthreads();
    float aq[16], ak[16], av[16];
    #pragma unroll
    for (int i = 0; i < 16; i++) { aq[i] = bq[t]; ak[i] = bk[t]; av[i] = bv[t]; }
    for (int d = 0; d < DD; d++) {
        float wq = Wq[d * DD + t], wk = Wk[d * DD + t], wv = Wv[d * DD + t];
        #pragma unroll
        for (int i = 0; i < 16; i++) {
            float hv = h[i][d];
            aq[i] += hv * wq;
            ak[i] += hv * wk;
            av[i] += hv * wv;
        }
    }
    #pragma unroll
    for (int i = 0; i < 16; i++) {
        g_Qb[(r0 + i) * DD + t] = aq[i];
        g_Kb[(r0 + i) * DD + t] = ak[i];
        g_Vb[(r0 + i) * DD + t] = av[i];
    }
}

// ---------------- attention: scalar 3x3 per sequence -------------------------
__global__ void attn_kernel() {
    __shared__ float q[3][DD], k[3][DD], v[3][DD], a[9];
    int s = blockIdx.x, t = threadIdx.x;
    int base = s * 3 * DD;
    #pragma unroll
    for (int i = 0; i < 3; i++) {
        q[i][t] = g_Qb[base + i * DD + t];
        k[i][t] = g_Kb[base + i * DD + t];
        v[i][t] = g_Vb[base + i * DD + t];
    }
    __syncthreads();
    if (t < 9) {
        int i = t / 3, j = t % 3;
        float acc = 0.f;
        for (int d = 0; d < DD; d++) acc += q[i][d] * k[j][d];
        a[t] = acc * 0.125f;           // / sqrt(dk), dk = 64
    }
    __syncthreads();
    if (t < 3) {
        float m0 = fmaxf(a[t*3], fmaxf(a[t*3+1], a[t*3+2]));
        float e0 = expf(a[t*3]   - m0);
        float e1 = expf(a[t*3+1] - m0);
        float e2 = expf(a[t*3+2] - m0);
        float inv = 1.f / (e0 + e1 + e2);
        a[t*3] = e0 * inv; a[t*3+1] = e1 * inv; a[t*3+2] = e2 * inv;
    }
    __syncthreads();
    #pragma unroll
    for (int i = 0; i < 3; i++)
        g_Ab[base + i * DD + t] = a[i*3] * v[0][t] + a[i*3+1] * v[1][t] + a[i*3+2] * v[2][t];
}

// ---------------- O projection: H = Ab @ Wo + bo, 16 rows per block ----------
__global__ void oproj_kernel(const float* __restrict__ Wo, const float* __restrict__ bo) {
    __shared__ float h[16][DD];
    int r0 = blockIdx.x * 16, t = threadIdx.x;
    #pragma unroll
    for (int i = 0; i < 16; i++) h[i][t] = g_Ab[(r0 + i) * DD + t];
    __syncthreads();
    float ao[16];
    #pragma unroll
    for (int i = 0; i < 16; i++) ao[i] = bo[t];
    for (int d = 0; d < DD; d++) {
        float wo = Wo[d * DD + t];
        #pragma unroll
        for (int i = 0; i < 16; i++) ao[i] += h[i][d] * wo;
    }
    #pragma unroll
    for (int i = 0; i < 16; i++) g_H[(r0 + i) * DD + t] = ao[i];
}

// ---------------- dense on CLS rows: x = tanh(H[:,0,:] @ W + b) --------------
__global__ void dense_kernel(const float* __restrict__ W, const float* __restrict__ b) {
    __shared__ float h[DD];
    int s = blockIdx.x, t = threadIdx.x;
    h[t] = g_H[s * 3 * DD + t];       // CLS row
    __syncthreads();
    float acc = b[t];
    for (int d = 0; d < DD; d++) acc += h[d] * W[d * DD + t];
    g_x[s * DD + t] = tanhf(acc);
}

// ---------------- final: logits mean + retrieval mix -------------------------
__global__ void final_kernel(const float* __restrict__ out_w,
                             const float* __restrict__ out_b,
                             float* __restrict__ out) {
    __shared__ float lg[36];
    int b = blockIdx.x, t = threadIdx.x;   // 36 threads
    int k = t / NLAB, l = t % NLAB;
    float acc = out_b[l];
    const float* x = &g_x[(b * 3 + k) * DD];
    for (int d = 0; d < DD; d++) acc += x[d] * out_w[d * NLAB + l];
    lg[t] = acc;
    __syncthreads();
    if (t < NLAB) {
        float mean = (lg[t] + lg[NLAB + t] + lg[2 * NLAB + t]) * (1.f / 3.f);
        int l0 = g_lab[b * 3], l1 = g_lab[b * 3 + 1], l2 = g_lab[b * 3 + 2];
        float cnt = (float)((l0 == t) + (l1 == t) + (l2 == t));
        out[b * NLAB + t] = 0.5f * mean + 0.5f * (cnt * (1.f / 3.f));
    }
}

// ---------------- launcher ---------------------------------------------------
extern "C" void kernel_launch(void* const* d_in, const int* in_sizes, int n_in,
                              void* d_out, int out_size) {
    const float* queries = (const float*)d_in[0];
    const float* weight  = (const float*)d_in[1];
    const int*   label   = (const int*)  d_in[2];
    const float* Wq      = (const float*)d_in[3];
    const float* bq      = (const float*)d_in[4];
    const float* Wk      = (const float*)d_in[5];
    const float* bk      = (const float*)d_in[6];
    const float* Wv      = (const float*)d_in[7];
    const float* bv      = (const float*)d_in[8];
    const float* Wo      = (const float*)d_in[9];
    const float* bo      = (const float*)d_in[10];
    const float* dense_w = (const float*)d_in[11];
    const float* dense_b = (const float*)d_in[12];
    const float* out_w   = (const float*)d_in[13];
    const float* out_b   = (const float*)d_in[14];
    float* out = (float*)d_out;

    normalize_kernel<<<BB, DD>>>(queries);
    sims_topk_kernel<<<dim3(GX, 4), 256>>>(weight);
    topk_merge_kernel<<<BB, 160>>>(label);
    build_h_kernel<<<NSEQ, DD>>>(queries, weight);

    for (int l = 0; l < 2; l++) {
        qkv_kernel<<<MROWS / 16, DD>>>(Wq + l * DD * DD, bq + l * DD,
                                       Wk + l * DD * DD, bk + l * DD,
                                       Wv + l * DD * DD, bv + l * DD);
        attn_kernel<<<NSEQ, DD>>>();
        oproj_kernel<<<MROWS / 16, DD>>>(Wo + l * DD * DD, bo + l * DD);
    }
    dense_kernel<<<NSEQ, DD>>>(dense_w, dense_b);
    final_kernel<<<BB, 36>>>(out_w, out_b, out);
}

// round 8
// speedup vs baseline: 1.5779x; 1.5779x over previous
#include <cuda_runtime.h>
#include <cuda_bf16.h>
#include <float.h>
#include <math.h>

// ---------------------------------------------------------------------------
// MEATransformer: top-3 retrieval over 500K cosine sims + tiny 2-layer
// transformer (768 seqs x 3 tokens x 256) + logits/retrieval mix.
// Round 7: revert cp.async (regressed). q tile resident in smem (loaded once),
// w double-buffered via register prefetch, single barrier per stage.
// Inner FFMA2 loop identical to the 2089us version (bit-identical results).
// ---------------------------------------------------------------------------

#define NN       500000
#define DD       256
#define BB       256
#define KK       3
#define NLAB     12
#define CT       128            // columns per tile in sims kernel
#define NTILES   3907           // ceil(500000/128)
#define GX       148            // sims gridDim.x (partials width) = 2 exact waves
#define NSEQ     768            // B*K
#define MROWS    2304           // NSEQ*3 token rows

#define QSTRIDE  260            // q smem row stride (floats): 16B-aligned, bank-safe
#define SIMS_SMEM_FLOATS (64 * QSTRIDE + 2 * 32 * CT)
#define SIMS_SMEM_BYTES  (SIMS_SMEM_FLOATS * 4)

// ---------------- device scratch (no cudaMalloc allowed) -------------------
__device__ float g_qn   [BB * DD];
__device__ float g_pv   [BB * GX * 3];
__device__ int   g_pi   [BB * GX * 3];
__device__ float g_score[NSEQ];
__device__ int   g_idx  [NSEQ];
__device__ int   g_lab  [NSEQ];
__device__ float g_H    [MROWS * DD];
__device__ float g_Qb   [MROWS * DD];
__device__ float g_Kb   [MROWS * DD];
__device__ float g_Vb   [MROWS * DD];
__device__ float g_Ab   [MROWS * DD];
__device__ float g_x    [NSEQ * DD];

// ---------------- f32x2 helpers ---------------------------------------------
__device__ __forceinline__ unsigned long long bcast2(float v) {
    unsigned long long r;
    asm("mov.b64 %0, {%1,%1};" : "=l"(r) : "f"(v));
    return r;
}
__device__ __forceinline__ void unpack2(unsigned long long v, float& lo, float& hi) {
    asm("mov.b64 {%0,%1}, %2;" : "=f"(lo), "=f"(hi) : "l"(v));
}
__device__ __forceinline__ void ffma2(unsigned long long& d,
                                      unsigned long long a,
                                      unsigned long long b) {
    asm("fma.rn.f32x2 %0, %1, %2, %0;" : "+l"(d) : "l"(a), "l"(b));
}

// ---------------- top-3 helpers ----------------------------------------------
__device__ __forceinline__ bool better(float v1, int i1, float v2, int i2) {
    return (v1 > v2) || (v1 == v2 && i1 < i2);   // jax top_k: ties -> lower idx
}
__device__ __forceinline__ void ins3(float v, int i,
                                     float& v0, int& i0,
                                     float& v1, int& i1,
                                     float& v2, int& i2) {
    if (better(v, i, v2, i2)) {
        if (better(v, i, v1, i1)) {
            v2 = v1; i2 = i1;
            if (better(v, i, v0, i0)) { v1 = v0; i1 = i0; v0 = v; i0 = i; }
            else                      { v1 = v;  i1 = i; }
        } else { v2 = v; i2 = i; }
    }
}
__device__ __forceinline__ void merge3(float& a0, int& x0, float& a1, int& x1,
                                       float& a2, int& x2,
                                       float b0, int y0, float b1, int y1,
                                       float b2, int y2) {
    float o0, o1, o2; int p0, p1, p2;
    if (better(a0, x0, b0, y0)) { o0 = a0; p0 = x0; a0 = a1; x0 = x1; a1 = a2; x1 = x2; a2 = -FLT_MAX; x2 = 0x7fffffff; }
    else                        { o0 = b0; p0 = y0; b0 = b1; y0 = y1; b1 = b2; y1 = y2; b2 = -FLT_MAX; y2 = 0x7fffffff; }
    if (better(a0, x0, b0, y0)) { o1 = a0; p1 = x0; a0 = a1; x0 = x1; }
    else                        { o1 = b0; p1 = y0; b0 = b1; y0 = y1; }
    if (better(a0, x0, b0, y0)) { o2 = a0; p2 = x0; }
    else                        { o2 = b0; p2 = y0; }
    a0 = o0; x0 = p0; a1 = o1; x1 = p1; a2 = o2; x2 = p2;
}

// ---------------- kernel 1: normalize queries -------------------------------
__global__ void normalize_kernel(const float* __restrict__ q) {
    __shared__ float ws[8];
    int b = blockIdx.x, t = threadIdx.x;
    float v = q[b * DD + t];
    float s = v * v;
    #pragma unroll
    for (int o = 16; o; o >>= 1) s += __shfl_xor_sync(0xffffffffu, s, o);
    if ((t & 31) == 0) ws[t >> 5] = s;
    __syncthreads();
    float tot = 0.f;
    #pragma unroll
    for (int w = 0; w < 8; w++) tot += ws[w];
    g_qn[b * DD + t] = v / sqrtf(tot);
}

// ---------------- kernel 2: sims GEMM + streaming top-3 ---------------------
// 256 threads (16 tx x 16 ty); tile 64 queries x 128 columns; micro-tile
// 4 rows x 8 cols via f32x2. q tile resident in smem (loaded once).
// w chunks double-buffered: LDG.128 prefetch into regs overlaps compute,
// STS at stage top, ONE __syncthreads per stage.
extern __shared__ float s_dyn[];
__global__ void __launch_bounds__(256, 2)
sims_topk_kernel(const float* __restrict__ w) {
    float* qs  = s_dyn;                    // 64 x QSTRIDE floats
    float* wsm = s_dyn + 64 * QSTRIDE;     // 2 x 32 x 128 floats

    const int tid = threadIdx.x;
    const int tx = tid & 15, ty = tid >> 4;
    const int ty4 = ty * 4;
    const int qrow0 = blockIdx.y * 64;

    // ---- load q tile once: 64 rows x 256 d ----
    #pragma unroll
    for (int j = 0; j < 16; j++) {
        int id = tid + j * 256;
        int r = id >> 6, c4 = id & 63;
        float4 v = *(const float4*)(g_qn + (qrow0 + r) * DD + c4 * 4);
        *(float4*)(qs + r * QSTRIDE + c4 * 4) = v;
    }

    const int ntiles_mine = (NTILES - blockIdx.x + GX - 1) / GX;

    float tv[4][3]; int ti3[4][3];
    #pragma unroll
    for (int r = 0; r < 4; r++)
        #pragma unroll
        for (int j = 0; j < 3; j++) { tv[r][j] = -FLT_MAX; ti3[r][j] = 0x7fffffff; }

    float4 wr[4];   // prefetch registers for next w stage

    // ---- prefetch stage (tile t, chunk dk) into wr ----
    auto ldg_stage = [&](int t, int dk) {
        const int col0 = t * CT;
        #pragma unroll
        for (int j = 0; j < 4; j++) {
            int id = tid + j * 256;
            int r = id >> 5, c4 = id & 31;
            int col = col0 + c4 * 4;
            if (col < NN)
                wr[j] = *(const float4*)(w + (long)(dk * 32 + r) * NN + col);
            else
                wr[j] = make_float4(0.f, 0.f, 0.f, 0.f);
        }
    };
    auto sts_stage = [&](int buf) {
        #pragma unroll
        for (int j = 0; j < 4; j++) {
            int id = tid + j * 256;
            int r = id >> 5, c4 = id & 31;
            *(float4*)(wsm + buf * (32 * CT) + r * CT + c4 * 4) = wr[j];
        }
    };

    ldg_stage(blockIdx.x, 0);   // prologue

    int t = blockIdx.x;
    int stage = 0;
    for (int ti = 0; ti < ntiles_mine; ti++, t += GX) {
        const int col0 = t * CT;
        unsigned long long acc[4][4];
        #pragma unroll
        for (int r = 0; r < 4; r++)
            #pragma unroll
            for (int p = 0; p < 4; p++) acc[r][p] = 0ull;

        for (int dk = 0; dk < 8; dk++, stage++) {
            const int buf = stage & 1;
            sts_stage(buf);
            __syncthreads();   // STS visible; (induction) compute of stage-2 done
            if (dk < 7)                      ldg_stage(t, dk + 1);
            else if (ti + 1 < ntiles_mine)   ldg_stage(t + GX, 0);

            const float* wsf = wsm + buf * (32 * CT);
            const float* q0 = qs + (ty4 + 0) * QSTRIDE + dk * 32;
            const float* q1 = qs + (ty4 + 1) * QSTRIDE + dk * 32;
            const float* q2 = qs + (ty4 + 2) * QSTRIDE + dk * 32;
            const float* q3 = qs + (ty4 + 3) * QSTRIDE + dk * 32;
            #pragma unroll
            for (int d = 0; d < 32; d++) {
                const ulonglong2 a = *(const ulonglong2*)(wsf + d * CT + tx * 4);
                const ulonglong2 b = *(const ulonglong2*)(wsf + d * CT + 64 + tx * 4);
                unsigned long long qv;
                qv = bcast2(q0[d]);
                ffma2(acc[0][0], qv, a.x); ffma2(acc[0][1], qv, a.y);
                ffma2(acc[0][2], qv, b.x); ffma2(acc[0][3], qv, b.y);
                qv = bcast2(q1[d]);
                ffma2(acc[1][0], qv, a.x); ffma2(acc[1][1], qv, a.y);
                ffma2(acc[1][2], qv, b.x); ffma2(acc[1][3], qv, b.y);
                qv = bcast2(q2[d]);
                ffma2(acc[2][0], qv, a.x); ffma2(acc[2][1], qv, a.y);
                ffma2(acc[2][2], qv, b.x); ffma2(acc[2][3], qv, b.y);
                qv = bcast2(q3[d]);
                ffma2(acc[3][0], qv, a.x); ffma2(acc[3][1], qv, a.y);
                ffma2(acc[3][2], qv, b.x); ffma2(acc[3][3], qv, b.y);
            }
        }
        // streaming top-3 insertion
        // acc[rr][0] -> cols col0+tx*4 +0/+1 ; acc[rr][1] -> +2/+3
        // acc[rr][2] -> cols col0+64+tx*4 +0/+1 ; acc[rr][3] -> +2/+3
        #pragma unroll
        for (int rr = 0; rr < 4; rr++) {
            #pragma unroll
            for (int p = 0; p < 4; p++) {
                float lo, hi;
                unpack2(acc[rr][p], lo, hi);
                int grp = p >> 1;
                int c0 = col0 + grp * 64 + tx * 4 + (p & 1) * 2;
                if (c0 < NN)
                    ins3(lo, c0, tv[rr][0], ti3[rr][0], tv[rr][1], ti3[rr][1], tv[rr][2], ti3[rr][2]);
                if (c0 + 1 < NN)
                    ins3(hi, c0 + 1, tv[rr][0], ti3[rr][0], tv[rr][1], ti3[rr][1], tv[rr][2], ti3[rr][2]);
            }
        }
    }

    #pragma unroll
    for (int rr = 0; rr < 4; rr++) {
        #pragma unroll
        for (int off = 8; off >= 1; off >>= 1) {
            float b0 = __shfl_xor_sync(0xffffffffu, tv[rr][0], off, 16);
            float b1 = __shfl_xor_sync(0xffffffffu, tv[rr][1], off, 16);
            float b2 = __shfl_xor_sync(0xffffffffu, tv[rr][2], off, 16);
            int   y0 = __shfl_xor_sync(0xffffffffu, ti3[rr][0], off, 16);
            int   y1 = __shfl_xor_sync(0xffffffffu, ti3[rr][1], off, 16);
            int   y2 = __shfl_xor_sync(0xffffffffu, ti3[rr][2], off, 16);
            merge3(tv[rr][0], ti3[rr][0], tv[rr][1], ti3[rr][1], tv[rr][2], ti3[rr][2],
                   b0, y0, b1, y1, b2, y2);
        }
        if (tx == 0) {
            int q = qrow0 + ty4 + rr;
            int base = (q * GX + blockIdx.x) * 3;
            #pragma unroll
            for (int j = 0; j < 3; j++) { g_pv[base + j] = tv[rr][j]; g_pi[base + j] = ti3[rr][j]; }
        }
    }
}

// ---------------- kernel 3: merge partial top-3 per query -------------------
// 160 threads (5 warps); lanes t >= GX hold neutral values.
__global__ void topk_merge_kernel(const int* __restrict__ label) {
    __shared__ float sv[5][3];
    __shared__ int   si[5][3];
    int b = blockIdx.x, t = threadIdx.x;
    float v0 = -FLT_MAX, v1 = -FLT_MAX, v2 = -FLT_MAX;
    int   i0 = 0x7fffffff, i1 = 0x7fffffff, i2 = 0x7fffffff;
    if (t < GX) {
        int base = (b * GX + t) * 3;
        v0 = g_pv[base];     i0 = g_pi[base];
        v1 = g_pv[base + 1]; i1 = g_pi[base + 1];
        v2 = g_pv[base + 2]; i2 = g_pi[base + 2];
    }
    #pragma unroll
    for (int off = 16; off >= 1; off >>= 1) {
        float b0 = __shfl_xor_sync(0xffffffffu, v0, off);
        float b1 = __shfl_xor_sync(0xffffffffu, v1, off);
        float b2 = __shfl_xor_sync(0xffffffffu, v2, off);
        int   y0 = __shfl_xor_sync(0xffffffffu, i0, off);
        int   y1 = __shfl_xor_sync(0xffffffffu, i1, off);
        int   y2 = __shfl_xor_sync(0xffffffffu, i2, off);
        merge3(v0, i0, v1, i1, v2, i2, b0, y0, b1, y1, b2, y2);
    }
    int warp = t >> 5;
    if ((t & 31) == 0) { sv[warp][0] = v0; si[warp][0] = i0; sv[warp][1] = v1; si[warp][1] = i1; sv[warp][2] = v2; si[warp][2] = i2; }
    __syncthreads();
    if (t == 0) {
        float f0 = -FLT_MAX, f1 = -FLT_MAX, f2 = -FLT_MAX;
        int   j0 = 0x7fffffff, j1 = 0x7fffffff, j2 = 0x7fffffff;
        for (int wp = 0; wp < 5; wp++)
            for (int e = 0; e < 3; e++)
                ins3(sv[wp][e], si[wp][e], f0, j0, f1, j1, f2, j2);
        float fv[3] = {f0, f1, f2}; int fi[3] = {j0, j1, j2};
        for (int k = 0; k < 3; k++) {
            g_score[b * 3 + k] = fv[k];
            g_idx[b * 3 + k]   = fi[k];
            g_lab[b * 3 + k]   = label[fi[k]];
        }
    }
}

// ---------------- kernel 4: build H (gather) ---------------------------------
__global__ void build_h_kernel(const float* __restrict__ queries,
                               const float* __restrict__ w) {
    int s = blockIdx.x;       // 0..767
    int d = threadIdx.x;      // 0..255
    int b = s / KK;
    int lab = g_lab[s];
    float score = g_score[s];
    int idx = g_idx[s];
    float* Hrow = &g_H[s * 3 * DD];
    Hrow[d]           = (d == lab) ? score : 0.f;   // CLS token
    Hrow[DD + d]      = queries[b * DD + d];        // query token
    Hrow[2 * DD + d]  = w[d * NN + idx];            // retrieved token
}

// ---------------- tail: fused Q/K/V matvec, 16 rows per block ----------------
__global__ void qkv_kernel(const float* __restrict__ Wq, const float* __restrict__ bq,
                           const float* __restrict__ Wk, const float* __restrict__ bk,
                           const float* __restrict__ Wv, const float* __restrict__ bv) {
    __shared__ float h[16][DD];
    int r0 = blockIdx.x * 16, t = threadIdx.x;
    #pragma unroll
    for (int i = 0; i < 16; i++) h[i][t] = g_H[(r0 + i) * DD + t];
    __syncthreads();
    float aq[16], ak[16], av[16];
    #pragma unroll
    for (int i = 0; i < 16; i++) { aq[i] = bq[t]; ak[i] = bk[t]; av[i] = bv[t]; }
    for (int d = 0; d < DD; d++) {
        float wq = Wq[d * DD + t], wk = Wk[d * DD + t], wv = Wv[d * DD + t];
        #pragma unroll
        for (int i = 0; i < 16; i++) {
            float hv = h[i][d];
            aq[i] += hv * wq;
            ak[i] += hv * wk;
            av[i] += hv * wv;
        }
    }
    #pragma unroll
    for (int i = 0; i < 16; i++) {
        g_Qb[(r0 + i) * DD + t] = aq[i];
        g_Kb[(r0 + i) * DD + t] = ak[i];
        g_Vb[(r0 + i) * DD + t] = av[i];
    }
}

// ---------------- attention: scalar 3x3 per sequence -------------------------
__global__ void attn_kernel() {
    __shared__ float q[3][DD], k[3][DD], v[3][DD], a[9];
    int s = blockIdx.x, t = threadIdx.x;
    int base = s * 3 * DD;
    #pragma unroll
    for (int i = 0; i < 3; i++) {
        q[i][t] = g_Qb[base + i * DD + t];
        k[i][t] = g_Kb[base + i * DD + t];
        v[i][t] = g_Vb[base + i * DD + t];
    }
    __syncthreads();
    if (t < 9) {
        int i = t / 3, j = t % 3;
        float acc = 0.f;
        for (int d = 0; d < DD; d++) acc += q[i][d] * k[j][d];
        a[t] = acc * 0.125f;           // / sqrt(dk), dk = 64
    }
    __syncthreads();
    if (t < 3) {
        float m0 = fmaxf(a[t*3], fmaxf(a[t*3+1], a[t*3+2]));
        float e0 = expf(a[t*3]   - m0);
        float e1 = expf(a[t*3+1] - m0);
        float e2 = expf(a[t*3+2] - m0);
        float inv = 1.f / (e0 + e1 + e2);
        a[t*3] = e0 * inv; a[t*3+1] = e1 * inv; a[t*3+2] = e2 * inv;
    }
    __syncthreads();
    #pragma unroll
    for (int i = 0; i < 3; i++)
        g_Ab[base + i * DD + t] = a[i*3] * v[0][t] + a[i*3+1] * v[1][t] + a[i*3+2] * v[2][t];
}

// ---------------- O projection: H = Ab @ Wo + bo, 16 rows per block ----------
__global__ void oproj_kernel(const float* __restrict__ Wo, const float* __restrict__ bo) {
    __shared__ float h[16][DD];
    int r0 = blockIdx.x * 16, t = threadIdx.x;
    #pragma unroll
    for (int i = 0; i < 16; i++) h[i][t] = g_Ab[(r0 + i) * DD + t];
    __syncthreads();
    float ao[16];
    #pragma unroll
    for (int i = 0; i < 16; i++) ao[i] = bo[t];
    for (int d = 0; d < DD; d++) {
        float wo = Wo[d * DD + t];
        #pragma unroll
        for (int i = 0; i < 16; i++) ao[i] += h[i][d] * wo;
    }
    #pragma unroll
    for (int i = 0; i < 16; i++) g_H[(r0 + i) * DD + t] = ao[i];
}

// ---------------- dense on CLS rows: x = tanh(H[:,0,:] @ W + b) --------------
__global__ void dense_kernel(const float* __restrict__ W, const float* __restrict__ b) {
    __shared__ float h[DD];
    int s = blockIdx.x, t = threadIdx.x;
    h[t] = g_H[s * 3 * DD + t];       // CLS row
    __syncthreads();
    float acc = b[t];
    for (int d = 0; d < DD; d++) acc += h[d] * W[d * DD + t];
    g_x[s * DD + t] = tanhf(acc);
}

// ---------------- final: logits mean + retrieval mix -------------------------
__global__ void final_kernel(const float* __restrict__ out_w,
                             const float* __restrict__ out_b,
                             float* __restrict__ out) {
    __shared__ float lg[36];
    int b = blockIdx.x, t = threadIdx.x;   // 36 threads
    int k = t / NLAB, l = t % NLAB;
    float acc = out_b[l];
    const float* x = &g_x[(b * 3 + k) * DD];
    for (int d = 0; d < DD; d++) acc += x[d] * out_w[d * NLAB + l];
    lg[t] = acc;
    __syncthreads();
    if (t < NLAB) {
        float mean = (lg[t] + lg[NLAB + t] + lg[2 * NLAB + t]) * (1.f / 3.f);
        int l0 = g_lab[b * 3], l1 = g_lab[b * 3 + 1], l2 = g_lab[b * 3 + 2];
        float cnt = (float)((l0 == t) + (l1 == t) + (l2 == t));
        out[b * NLAB + t] = 0.5f * mean + 0.5f * (cnt * (1.f / 3.f));
    }
}

// ---------------- launcher ---------------------------------------------------
extern "C" void kernel_launch(void* const* d_in, const int* in_sizes, int n_in,
                              void* d_out, int out_size) {
    const float* queries = (const float*)d_in[0];
    const float* weight  = (const float*)d_in[1];
    const int*   label   = (const int*)  d_in[2];
    const float* Wq      = (const float*)d_in[3];
    const float* bq      = (const float*)d_in[4];
    const float* Wk      = (const float*)d_in[5];
    const float* bk      = (const float*)d_in[6];
    const float* Wv      = (const float*)d_in[7];
    const float* bv      = (const float*)d_in[8];
    const float* Wo      = (const float*)d_in[9];
    const float* bo      = (const float*)d_in[10];
    const float* dense_w = (const float*)d_in[11];
    const float* dense_b = (const float*)d_in[12];
    const float* out_w   = (const float*)d_in[13];
    const float* out_b   = (const float*)d_in[14];
    float* out = (float*)d_out;

    static bool attr_set = false;
    if (!attr_set) {
        cudaFuncSetAttribute(sims_topk_kernel,
                             cudaFuncAttributeMaxDynamicSharedMemorySize,
                             SIMS_SMEM_BYTES);
        attr_set = true;
    }

    normalize_kernel<<<BB, DD>>>(queries);
    sims_topk_kernel<<<dim3(GX, 4), 256, SIMS_SMEM_BYTES>>>(weight);
    topk_merge_kernel<<<BB, 160>>>(label);
    build_h_kernel<<<NSEQ, DD>>>(queries, weight);

    for (int l = 0; l < 2; l++) {
        qkv_kernel<<<MROWS / 16, DD>>>(Wq + l * DD * DD, bq + l * DD,
                                       Wk + l * DD * DD, bk + l * DD,
                                       Wv + l * DD * DD, bv + l * DD);
        attn_kernel<<<NSEQ, DD>>>();
        oproj_kernel<<<MROWS / 16, DD>>>(Wo + l * DD * DD, bo + l * DD);
    }
    dense_kernel<<<NSEQ, DD>>>(dense_w, dense_b);
    final_kernel<<<BB, 36>>>(out_w, out_b, out);
}